// round 1
// baseline (speedup 1.0000x reference)
#include <cuda_runtime.h>
#include <cstdint>

#define Hh 512
#define Wd 512
#define Cc 80
#define HW (Hh * Wd)
#define NBINS (1 << 18)
#define SURV_CAP (4u << 20)     /* 4M survivors max (expect ~2.33M) */
#define CAND_CAP 65536
#define FLATBITS 25
#define FLATMASK ((1u << FLATBITS) - 1)

// ---- scratch (device globals; no runtime allocation) ----
__device__ unsigned int       g_hist[NBINS];
__device__ unsigned long long g_surv[SURV_CAP];
__device__ unsigned long long g_cand[CAND_CAP];
__device__ unsigned int       g_nsurv;
__device__ unsigned int       g_ncand;
__device__ unsigned int       g_thresh;   // key threshold (not bin)

// monotonic float->uint key (total order matching float <)
__device__ __forceinline__ unsigned int fkey(float v) {
    unsigned int u = __float_as_uint(v);
    return (u & 0x80000000u) ? ~u : (u | 0x80000000u);
}
__device__ __forceinline__ float fkey_inv(unsigned int k) {
    unsigned int u = (k & 0x80000000u) ? (k ^ 0x80000000u) : ~k;
    return __uint_as_float(u);
}

// ---- K0: clear scratch ----
__global__ void clear_kernel() {
    int i = blockIdx.x * blockDim.x + threadIdx.x;
    if (i < NBINS) g_hist[i] = 0u;
    if (i == 0) { g_nsurv = 0u; g_ncand = 0u; g_thresh = 0u; }
}

// ---- K1: NMS scan; append survivors + histogram ----
__global__ __launch_bounds__(256) void nms_kernel(const float* __restrict__ hmap) {
    int x = blockIdx.x * 32 + threadIdx.x;
    int y = blockIdx.y * 8 + threadIdx.y;
    int c = blockIdx.z;
    const float* __restrict__ p = hmap + (size_t)c * HW;
    float v = __ldg(&p[y * Wd + x]);

    int x0 = x > 0 ? x - 1 : 0, x1 = x < Wd - 1 ? x + 1 : Wd - 1;
    int y0 = y > 0 ? y - 1 : 0, y1 = y < Hh - 1 ? y + 1 : Hh - 1;
    bool keep = true;
    #pragma unroll 3
    for (int yy = y0; yy <= y1; yy++) {
        #pragma unroll 3
        for (int xx = x0; xx <= x1; xx++) {
            if (__ldg(&p[yy * Wd + xx]) > v) { keep = false; }
        }
    }

    unsigned int key = 0u;
    if (keep) {
        key = fkey(v);
        atomicAdd(&g_hist[key >> 14], 1u);
    }
    // warp-aggregated survivor append
    unsigned int mask = __ballot_sync(0xffffffffu, keep);
    if (mask) {
        int lane = threadIdx.x & 31;  // blockDim.x==32 -> lane == threadIdx.x
        int leader = __ffs(mask) - 1;
        unsigned int base = 0;
        if (lane == leader) base = atomicAdd(&g_nsurv, (unsigned int)__popc(mask));
        base = __shfl_sync(0xffffffffu, base, leader);
        if (keep) {
            unsigned int pos = base + __popc(mask & ((1u << lane) - 1u));
            if (pos < SURV_CAP) {
                unsigned int flat = (unsigned int)c * HW + (unsigned int)(y * Wd + x);
                unsigned long long e =
                    ((unsigned long long)key << FLATBITS) | (FLATMASK - flat);
                g_surv[pos] = e;
            }
        }
    }
}

// ---- K2: find key threshold for top-K via histogram suffix scan (1 block) ----
__global__ void thresh_kernel(int K) {
    __shared__ unsigned int csum[1024];
    int t = threadIdx.x;
    unsigned int s = 0;
    int b0 = t * (NBINS / 1024);
    for (int b = b0; b < b0 + (NBINS / 1024); b++) s += g_hist[b];
    csum[t] = s;
    __syncthreads();
    if (t == 0) {
        unsigned int cum = 0;
        int tc = -1;
        for (int i = 1023; i >= 0; i--) {
            if (cum + csum[i] >= (unsigned int)K) { tc = i; break; }
            cum += csum[i];
        }
        unsigned int thr = 0;
        if (tc >= 0) {
            int lo = tc * (NBINS / 1024);
            for (int b = lo + (NBINS / 1024) - 1; b >= lo; b--) {
                cum += g_hist[b];
                if (cum >= (unsigned int)K) { thr = (unsigned int)b << 14; break; }
            }
        }
        g_thresh = thr;
    }
}

// ---- K3: filter survivors >= threshold into candidate buffer ----
__global__ void filter_kernel() {
    unsigned int n = min(g_nsurv, SURV_CAP);
    unsigned long long T = ((unsigned long long)g_thresh) << FLATBITS;
    for (unsigned int i = blockIdx.x * blockDim.x + threadIdx.x; i < n;
         i += gridDim.x * blockDim.x) {
        unsigned long long e = g_surv[i];
        if (e >= T) {
            unsigned int p = atomicAdd(&g_ncand, 1u);
            if (p < CAND_CAP) g_cand[p] = e;
        }
    }
}

// ---- K4: exact rank of each candidate; gather + write output (1 block) ----
__global__ void output_kernel(const float* __restrict__ regs,
                              const float* __restrict__ wh,
                              const float* __restrict__ rot,
                              float* __restrict__ out, int K) {
    __shared__ unsigned long long sk[5120];
    unsigned int n = min(g_ncand, (unsigned int)CAND_CAP);
    bool sh = (n <= 5120u);
    for (unsigned int i = threadIdx.x; i < n; i += blockDim.x)
        if (sh) sk[i] = g_cand[i];
    __syncthreads();

    for (unsigned int i = threadIdx.x; i < n; i += blockDim.x) {
        unsigned long long ki = sh ? sk[i] : g_cand[i];
        int rank = 0;
        for (unsigned int j = 0; j < n; j++) {
            unsigned long long kj = sh ? sk[j] : g_cand[j];
            rank += (kj > ki) ? 1 : 0;
        }
        if (rank < K) {
            unsigned int key = (unsigned int)(ki >> FLATBITS);
            unsigned int flat = FLATMASK - (unsigned int)(ki & FLATMASK);
            unsigned int c = flat / HW;
            unsigned int idx = flat - c * HW;
            float yf = (float)(idx >> 9);
            float xf = (float)(idx & 511u);
            float v = fkey_inv(key);
            float score = 1.0f / (1.0f + expf(-v));
            float* o = out + (size_t)rank * 7;
            o[0] = xf + __ldg(&regs[idx]);
            o[1] = yf + __ldg(&regs[HW + idx]);
            o[2] = __ldg(&wh[idx]);
            o[3] = __ldg(&wh[HW + idx]);
            o[4] = __ldg(&rot[idx]);
            o[5] = score;
            o[6] = (float)c;
        }
    }
}

extern "C" void kernel_launch(void* const* d_in, const int* in_sizes, int n_in,
                              void* d_out, int out_size) {
    const float* hmap = (const float*)d_in[0];
    const float* regs = (const float*)d_in[1];
    const float* wh   = (const float*)d_in[2];
    const float* rot  = (const float*)d_in[3];
    float* out = (float*)d_out;
    int K = out_size / 7;  // B=1; [B,K,7]

    clear_kernel<<<(NBINS + 255) / 256, 256>>>();
    dim3 blk(32, 8, 1);
    dim3 grd(Wd / 32, Hh / 8, Cc);
    nms_kernel<<<grd, blk>>>(hmap);
    thresh_kernel<<<1, 1024>>>(K);
    filter_kernel<<<1024, 256>>>();
    output_kernel<<<1, 1024>>>(regs, wh, rot, out, K);
}

// round 2
// speedup vs baseline: 6.8904x; 6.8904x over previous
#include <cuda_runtime.h>
#include <cstdint>
#include <math.h>

#define Hh 512
#define Wd 512
#define Cc 80
#define HW (Hh * Wd)
#define NBINS 1024
#define BINSHIFT 22
#define FLATBITS 25
#define FLATMASK ((1u << FLATBITS) - 1)
#define NWARPS_TOT 10240          /* 4 strips * 4 bands * 80 ch * 8 warps */
#define REGION 2048               /* 16 rows * 128 cols: exact worst case */
#define CAND_CAP 8192
#define SH_CAND 4096

// ---- scratch (device globals; no runtime allocation) ----
__device__ unsigned int       g_hist[NBINS];
__device__ unsigned int       g_wcnt[NWARPS_TOT];
__device__ unsigned long long g_surv[(size_t)NWARPS_TOT * REGION];
__device__ unsigned long long g_cand[CAND_CAP];
__device__ unsigned int       g_ncand;
__device__ unsigned long long g_thr;

// monotonic float->uint key (total order matching float <)
__device__ __forceinline__ unsigned int fkey(float v) {
    unsigned int u = __float_as_uint(v);
    return (u & 0x80000000u) ? ~u : (u | 0x80000000u);
}
__device__ __forceinline__ float fkey_inv(unsigned int k) {
    unsigned int u = (k & 0x80000000u) ? (k ^ 0x80000000u) : ~k;
    return __uint_as_float(u);
}

// ---- K0: clear histogram ----
__global__ void clear_kernel() {
    g_hist[threadIdx.x] = 0u;
}

// ---- K1: NMS scan (float4 + shuffle), regioned survivor append, smem hist ----
__global__ __launch_bounds__(256) void nms_kernel(const float* __restrict__ hmap) {
    __shared__ unsigned int shist[NBINS];
    const int lane = threadIdx.x;
    const int tid = threadIdx.y * 32 + lane;
    for (int i = tid; i < NBINS; i += 256) shist[i] = 0u;
    __syncthreads();

    const int c  = blockIdx.z;
    const int x0 = blockIdx.x * 128;
    const int y0 = blockIdx.y * 128 + threadIdx.y * 16;
    const float* __restrict__ base = hmap + (size_t)c * HW + x0;
    const unsigned int wgid =
        (((unsigned)blockIdx.z * gridDim.y + blockIdx.y) * gridDim.x + blockIdx.x) * 8
        + threadIdx.y;
    unsigned long long* __restrict__ reg = g_surv + (size_t)wgid * REGION;
    unsigned int wbase = 0;

    const float NEG = __int_as_float(0xff800000); // -inf

    float4 h0, h1, h2, v1, v2;

    auto loadrow = [&](int y, float4& h, float4& v) {
        if (y < 0 || y >= Hh) { h.x = h.y = h.z = h.w = NEG; return; }
        const float* q = base + y * Wd;
        v = *(const float4*)(q + lane * 4);
        float lft = __shfl_up_sync(0xffffffffu, v.w, 1);
        if (lane == 0)  lft = (x0 > 0) ? __ldg(q - 1) : NEG;
        float rgt = __shfl_down_sync(0xffffffffu, v.x, 1);
        if (lane == 31) rgt = (x0 + 128 < Wd) ? __ldg(q + 128) : NEG;
        h.x = fmaxf(fmaxf(lft,  v.x), v.y);
        h.y = fmaxf(fmaxf(v.x,  v.y), v.z);
        h.z = fmaxf(fmaxf(v.y,  v.z), v.w);
        h.w = fmaxf(fmaxf(v.z,  v.w), rgt);
    };

    float4 vdum;
    loadrow(y0 - 1, h0, vdum);
    loadrow(y0,     h1, v1);

#define EMIT(kp, val, flat)                                                   \
    {                                                                         \
        unsigned int mk = __ballot_sync(0xffffffffu, (kp));                   \
        if (kp) {                                                             \
            unsigned int key = fkey(val);                                     \
            atomicAdd(&shist[key >> BINSHIFT], 1u);                           \
            unsigned int pos = wbase + __popc(mk & ((1u << lane) - 1u));      \
            reg[pos] = ((unsigned long long)key << FLATBITS)                  \
                       | (unsigned long long)(FLATMASK - (flat));             \
        }                                                                     \
        wbase += __popc(mk);                                                  \
    }

#pragma unroll 4
    for (int r = 0; r < 16; r++) {
        int y = y0 + r;
        loadrow(y + 1, h2, v2);
        float m0 = fmaxf(fmaxf(h0.x, h1.x), h2.x);
        float m1 = fmaxf(fmaxf(h0.y, h1.y), h2.y);
        float m2 = fmaxf(fmaxf(h0.z, h1.z), h2.z);
        float m3 = fmaxf(fmaxf(h0.w, h1.w), h2.w);
        unsigned int fl = (unsigned)c * HW + (unsigned)y * Wd
                          + (unsigned)(x0 + lane * 4);
        EMIT(m0 == v1.x, v1.x, fl + 0u);
        EMIT(m1 == v1.y, v1.y, fl + 1u);
        EMIT(m2 == v1.z, v1.z, fl + 2u);
        EMIT(m3 == v1.w, v1.w, fl + 3u);
        h0 = h1; h1 = h2; v1 = v2;
    }
#undef EMIT

    if (lane == 0) g_wcnt[wgid] = wbase;
    __syncthreads();
    for (int i = tid; i < NBINS; i += 256) {
        unsigned int s = shist[i];
        if (s) atomicAdd(&g_hist[i], s);
    }
}

// ---- K2: threshold from 1024-bin histogram (1 block) ----
__global__ void thresh_kernel(int K) {
    __shared__ unsigned int s[NBINS];
    int t = threadIdx.x;
    s[t] = g_hist[t];
    __syncthreads();
    if (t == 0) {
        unsigned int cum = 0;
        int idx = 0;
        for (int i = NBINS - 1; i >= 0; i--) {
            cum += s[i];
            if (cum >= (unsigned int)K) { idx = i; break; }
        }
        g_thr = ((unsigned long long)((unsigned int)idx << BINSHIFT)) << FLATBITS;
        g_ncand = 0u;
    }
}

// ---- K3: filter per-warp survivor regions against threshold ----
__global__ void filter_kernel() {
    unsigned int b = blockIdx.x;
    unsigned int n = g_wcnt[b];
    unsigned long long T = g_thr;
    const unsigned long long* __restrict__ reg = g_surv + (size_t)b * REGION;
    for (unsigned int i = threadIdx.x; i < n; i += blockDim.x) {
        unsigned long long e = reg[i];
        if (e >= T) {
            unsigned int p = atomicAdd(&g_ncand, 1u);
            if (p < CAND_CAP) g_cand[p] = e;
        }
    }
}

// ---- K4: exact rank of each candidate; gather + write output (1 block) ----
__global__ void output_kernel(const float* __restrict__ regs,
                              const float* __restrict__ wh,
                              const float* __restrict__ rot,
                              float* __restrict__ out, int K) {
    __shared__ unsigned long long sk[SH_CAND];
    unsigned int n = min(g_ncand, (unsigned int)CAND_CAP);
    bool sh = (n <= (unsigned int)SH_CAND);
    if (sh)
        for (unsigned int i = threadIdx.x; i < n; i += blockDim.x)
            sk[i] = g_cand[i];
    __syncthreads();

    for (unsigned int i = threadIdx.x; i < n; i += blockDim.x) {
        unsigned long long ki = sh ? sk[i] : g_cand[i];
        int rank = 0;
        for (unsigned int j = 0; j < n; j++) {
            unsigned long long kj = sh ? sk[j] : g_cand[j];
            rank += (kj > ki) ? 1 : 0;
        }
        if (rank < K) {
            unsigned int key  = (unsigned int)(ki >> FLATBITS);
            unsigned int flat = FLATMASK - (unsigned int)(ki & FLATMASK);
            unsigned int c    = flat / HW;
            unsigned int idx  = flat - c * HW;
            float yf = (float)(idx >> 9);
            float xf = (float)(idx & 511u);
            float v = fkey_inv(key);
            float score = 1.0f / (1.0f + expf(-v));
            float* o = out + (size_t)rank * 7;
            o[0] = xf + __ldg(&regs[idx]);
            o[1] = yf + __ldg(&regs[HW + idx]);
            o[2] = __ldg(&wh[idx]);
            o[3] = __ldg(&wh[HW + idx]);
            o[4] = __ldg(&rot[idx]);
            o[5] = score;
            o[6] = (float)c;
        }
    }
}

extern "C" void kernel_launch(void* const* d_in, const int* in_sizes, int n_in,
                              void* d_out, int out_size) {
    const float* hmap = (const float*)d_in[0];
    const float* regs = (const float*)d_in[1];
    const float* wh   = (const float*)d_in[2];
    const float* rot  = (const float*)d_in[3];
    float* out = (float*)d_out;
    int K = out_size / 7;  // B=1; [B,K,7]

    clear_kernel<<<1, NBINS>>>();
    dim3 blk(32, 8, 1);
    dim3 grd(Wd / 128, Hh / 128, Cc);   // (4, 4, 80)
    nms_kernel<<<grd, blk>>>(hmap);
    thresh_kernel<<<1, NBINS>>>(K);
    filter_kernel<<<NWARPS_TOT, 64>>>();
    output_kernel<<<1, 1024>>>(regs, wh, rot, out, K);
}